// round 1
// baseline (speedup 1.0000x reference)
#include <cuda_runtime.h>

#define NATOMS 768
#define NM1 767
#define NEDGE (NATOMS * NM1)
#define DIM 64
#define NC 50
#define NCONV 3
#define ISLICE 96   // 768/96 = 8 source slices per destination

// -------- scratch (device globals; no runtime allocation) --------
__device__ float g_h[NATOMS * DIM];
__device__ float g_nw[NATOMS * DIM];
__device__ float g_agg[NATOMS * DIM];
__device__ float g_ha[NATOMS];

__device__ __forceinline__ float sp05(float x) {
    // softplus_bt(x, beta=0.5, thr=14): bx = 0.5x; bx>14 -> x else log1p(exp(bx))/0.5
    float bx = 0.5f * x;
    return (bx > 14.0f) ? x : 2.0f * log1pf(__expf(bx));
}

// ---------------- h0 = embedding[atom_types] ----------------
__global__ void k_embed(const int* __restrict__ at, const float* __restrict__ emb) {
    int n = blockIdx.x, t = threadIdx.x;
    g_h[n * DIM + t] = emb[at[n] * DIM + t];
}

// ---------------- nw = h @ W ; agg = 0 ----------------
__global__ void k_node_mm(const float* __restrict__ W) {
    int n = blockIdx.x, t = threadIdx.x;
    __shared__ float sh[DIM];
    sh[t] = g_h[n * DIM + t];
    __syncthreads();
    const float4* s4 = (const float4*)sh;
    float a0 = 0.f, a1 = 0.f, a2 = 0.f, a3 = 0.f;
#pragma unroll
    for (int k = 0; k < 16; k++) {
        float4 v = s4[k];
        a0 += v.x * W[(4 * k + 0) * DIM + t];
        a1 += v.y * W[(4 * k + 1) * DIM + t];
        a2 += v.z * W[(4 * k + 2) * DIM + t];
        a3 += v.w * W[(4 * k + 3) * DIM + t];
    }
    g_nw[n * DIM + t] = (a0 + a1) + (a2 + a3);
    g_agg[n * DIM + t] = 0.f;
}

// ---------------- fused edge filter + gather-mul + scatter-sum ----------------
// grid: (8 slices, 768 destinations), 64 threads (thread = dim).
// agg[j][t] = sum_{i != j} nw[i][t] * e(d_ij)[t]
__global__ __launch_bounds__(64) void k_edge_conv(
    const float* __restrict__ ed,
    const float* __restrict__ pw1, const float* __restrict__ pb1,
    const float* __restrict__ pw2, const float* __restrict__ pb2)
{
    int j = blockIdx.y, t = threadIdx.x;
    int i0 = blockIdx.x * ISLICE;

    // filter weights for this output dim, resident in registers
    float wa[52];
#pragma unroll
    for (int k = 0; k < 52; k++) wa[k] = (k < NC) ? pw1[k * DIM + t] : 0.f;
    float b1 = pb1[t];
    float wb[DIM];
#pragma unroll
    for (int k = 0; k < DIM; k++) wb[k] = pw2[k * DIM + t];
    float b2 = pb2[t];

    __shared__ float4 srbf[13];   // 52 floats (50 rbf + 2 zero pad)
    __shared__ float4 stt[16];    // 64 hidden

    float acc = 0.f;
    for (int i = i0; i < i0 + ISLICE; i++) {
        if (i == j) continue;                       // uniform across block
        int eidx = i * NM1 + j - (j > i ? 1 : 0);
        float dd = __ldg(&ed[eidx]);

        if (t < 52) {
            float r = 0.f;
            if (t < NC) {
                float x = dd - (float)t * (5.0f / 49.0f);
                r = __expf(-(49.0f / 5.0f) * x * x);
            }
            ((float*)srbf)[t] = r;
        }
        __syncthreads();

        float a0 = b1, a1 = 0.f, a2 = 0.f, a3 = 0.f;
#pragma unroll
        for (int k = 0; k < 13; k++) {
            float4 r4 = srbf[k];
            a0 += r4.x * wa[4 * k + 0];
            a1 += r4.y * wa[4 * k + 1];
            a2 += r4.z * wa[4 * k + 2];
            a3 += r4.w * wa[4 * k + 3];
        }
        float tv = sp05((a0 + a1) + (a2 + a3));
        ((float*)stt)[t] = tv;
        __syncthreads();

        float e0 = b2, e1 = 0.f, e2 = 0.f, e3 = 0.f;
#pragma unroll
        for (int k = 0; k < 16; k++) {
            float4 t4 = stt[k];
            e0 += t4.x * wb[4 * k + 0];
            e1 += t4.y * wb[4 * k + 1];
            e2 += t4.z * wb[4 * k + 2];
            e3 += t4.w * wb[4 * k + 3];
        }
        acc += __ldg(&g_nw[i * DIM + t]) * ((e0 + e1) + (e2 + e3));
    }
    atomicAdd(&g_agg[j * DIM + t], acc);
}

// ---------------- h += softplus(agg@qw1+qb1) @ qw2 + qb2 ----------------
__global__ void k_update(const float* __restrict__ qw1, const float* __restrict__ qb1,
                         const float* __restrict__ qw2, const float* __restrict__ qb2) {
    int n = blockIdx.x, t = threadIdx.x;
    __shared__ float sa[DIM], st[DIM];
    sa[t] = g_agg[n * DIM + t];
    __syncthreads();
    const float4* s4 = (const float4*)sa;
    float a0 = qb1[t], a1 = 0.f, a2 = 0.f, a3 = 0.f;
#pragma unroll
    for (int k = 0; k < 16; k++) {
        float4 v = s4[k];
        a0 += v.x * qw1[(4 * k + 0) * DIM + t];
        a1 += v.y * qw1[(4 * k + 1) * DIM + t];
        a2 += v.z * qw1[(4 * k + 2) * DIM + t];
        a3 += v.w * qw1[(4 * k + 3) * DIM + t];
    }
    st[t] = sp05((a0 + a1) + (a2 + a3));
    __syncthreads();
    const float4* t4 = (const float4*)st;
    float e0 = qb2[t], e1 = 0.f, e2 = 0.f, e3 = 0.f;
#pragma unroll
    for (int k = 0; k < 16; k++) {
        float4 v = t4[k];
        e0 += v.x * qw2[(4 * k + 0) * DIM + t];
        e1 += v.y * qw2[(4 * k + 1) * DIM + t];
        e2 += v.z * qw2[(4 * k + 2) * DIM + t];
        e3 += v.w * qw2[(4 * k + 3) * DIM + t];
    }
    g_h[n * DIM + t] += (e0 + e1) + (e2 + e3);
}

// ---------------- ha = (shiftsoftplus(h@au_w1+au_b1)) @ au_w2 + au_b2 ----------------
__global__ void k_atomupd(const float* __restrict__ w1, const float* __restrict__ b1,
                          const float* __restrict__ w2, const float* __restrict__ b2) {
    int n = blockIdx.x, t = threadIdx.x;
    __shared__ float sh[DIM];
    __shared__ float red[DIM];
    sh[t] = g_h[n * DIM + t];
    __syncthreads();
    const float4* s4 = (const float4*)sh;
    float a0 = b1[t], a1 = 0.f, a2 = 0.f, a3 = 0.f;
#pragma unroll
    for (int k = 0; k < 16; k++) {
        float4 v = s4[k];
        a0 += v.x * w1[(4 * k + 0) * DIM + t];
        a1 += v.y * w1[(4 * k + 1) * DIM + t];
        a2 += v.z * w1[(4 * k + 2) * DIM + t];
        a3 += v.w * w1[(4 * k + 3) * DIM + t];
    }
    float a = (a0 + a1) + (a2 + a3);
    // ShiftSoftplus: beta=1, thr=20, shift ln(2)
    float hid = ((a > 20.0f) ? a : log1pf(__expf(a))) - 0.69314718055994530942f;
    red[t] = hid * w2[t];   // au_w2: (64,1)
    __syncthreads();
    if (t < 32) red[t] += red[t + 32];
    __syncthreads();
    if (t < 32) {
        float v = red[t];
#pragma unroll
        for (int o = 16; o; o >>= 1) v += __shfl_xor_sync(0xffffffffu, v, o);
        if (t == 0) g_ha[n] = v + b2[0];
    }
}

// ---------------- readout: softmax(relu([ha_i, ha_j, rbf] @ W1 + b1) @ W2 + b2) ----------------
// warp per edge (grid-stride); lane handles hidden dims (lane, lane+32)
__global__ __launch_bounds__(128) void k_readout(
    const float* __restrict__ ed, const int* __restrict__ src, const int* __restrict__ dst,
    const float* __restrict__ w1, const float* __restrict__ b1,
    const float* __restrict__ w2, const float* __restrict__ b2,
    float2* __restrict__ out, int nwarps_total)
{
    __shared__ float4 rbf4[4][16];   // per-warp rbf buffer, 64 floats (50 + pad)
    int lane = threadIdx.x & 31;
    int wib = threadIdx.x >> 5;
    int gw = blockIdx.x * 4 + wib;
    int d0 = lane, d1 = lane + 32;

    float wsrc0 = w1[0 * DIM + d0], wdst0 = w1[1 * DIM + d0];
    float wsrc1 = w1[0 * DIM + d1], wdst1 = w1[1 * DIM + d1];
    float wr0[52], wr1[52];
#pragma unroll
    for (int k = 0; k < 52; k++) {
        wr0[k] = (k < NC) ? w1[(2 + k) * DIM + d0] : 0.f;
        wr1[k] = (k < NC) ? w1[(2 + k) * DIM + d1] : 0.f;
    }
    float bb0 = b1[d0], bb1 = b1[d1];
    float w200 = w2[d0 * 2 + 0], w201 = w2[d0 * 2 + 1];
    float w210 = w2[d1 * 2 + 0], w211 = w2[d1 * 2 + 1];
    float lb0 = b2[0], lb1 = b2[1];

    if (lane >= 18) ((float*)rbf4[wib])[lane + 32] = 0.f;  // pad indices 50..63
    __syncwarp();

    for (int e = gw; e < NEDGE; e += nwarps_total) {
        int i = __ldg(&src[e]), j = __ldg(&dst[e]);
        float dd = __ldg(&ed[e]);
        float hai = __ldg(&g_ha[i]), haj = __ldg(&g_ha[j]);

        {
            float x = dd - (float)lane * (5.0f / 49.0f);
            ((float*)rbf4[wib])[lane] = __expf(-(49.0f / 5.0f) * x * x);
            if (lane < 18) {
                float x2 = dd - (float)(lane + 32) * (5.0f / 49.0f);
                ((float*)rbf4[wib])[lane + 32] = __expf(-(49.0f / 5.0f) * x2 * x2);
            }
        }
        __syncwarp();

        float h0 = bb0 + hai * wsrc0 + haj * wdst0;
        float h1 = bb1 + hai * wsrc1 + haj * wdst1;
        float h0b = 0.f, h1b = 0.f;
#pragma unroll
        for (int k = 0; k < 13; k++) {
            float4 r = rbf4[wib][k];
            h0  += r.x * wr0[4 * k + 0];
            h0b += r.y * wr0[4 * k + 1];
            h0  += r.z * wr0[4 * k + 2];
            h0b += r.w * wr0[4 * k + 3];
            h1  += r.x * wr1[4 * k + 0];
            h1b += r.y * wr1[4 * k + 1];
            h1  += r.z * wr1[4 * k + 2];
            h1b += r.w * wr1[4 * k + 3];
        }
        __syncwarp();   // rbf reads done before next iteration's writes

        float r0 = fmaxf(h0 + h0b, 0.f), r1 = fmaxf(h1 + h1b, 0.f);
        float l0 = r0 * w200 + r1 * w210;
        float l1 = r0 * w201 + r1 * w211;
#pragma unroll
        for (int o = 16; o; o >>= 1) {
            l0 += __shfl_xor_sync(0xffffffffu, l0, o);
            l1 += __shfl_xor_sync(0xffffffffu, l1, o);
        }
        if (lane == 0) {
            l0 += lb0; l1 += lb1;
            float m = fmaxf(l0, l1);
            float e0 = __expf(l0 - m), e1 = __expf(l1 - m);
            float inv = 1.0f / (e0 + e1);
            out[e] = make_float2(e0 * inv, e1 * inv);
        }
    }
}

extern "C" void kernel_launch(void* const* d_in, const int* in_sizes, int n_in,
                              void* d_out, int out_size) {
    const int*   at   = (const int*)d_in[0];
    const float* ed   = (const float*)d_in[1];
    const int*   src  = (const int*)d_in[2];
    const int*   dst  = (const int*)d_in[3];
    const float* emb  = (const float*)d_in[4];
    const float* w1   = (const float*)d_in[5];
    const float* pw1  = (const float*)d_in[6];
    const float* pb1  = (const float*)d_in[7];
    const float* pw2  = (const float*)d_in[8];
    const float* pb2  = (const float*)d_in[9];
    const float* qw1  = (const float*)d_in[10];
    const float* qb1  = (const float*)d_in[11];
    const float* qw2  = (const float*)d_in[12];
    const float* qb2  = (const float*)d_in[13];
    const float* auw1 = (const float*)d_in[14];
    const float* aub1 = (const float*)d_in[15];
    const float* auw2 = (const float*)d_in[16];
    const float* aub2 = (const float*)d_in[17];
    const float* row1 = (const float*)d_in[18];
    const float* rob1 = (const float*)d_in[19];
    const float* row2 = (const float*)d_in[20];
    const float* rob2 = (const float*)d_in[21];

    k_embed<<<NATOMS, DIM>>>(at, emb);
    for (int l = 0; l < NCONV; l++) {
        k_node_mm<<<NATOMS, DIM>>>(w1 + l * DIM * DIM);
        k_edge_conv<<<dim3(NATOMS / ISLICE, NATOMS), DIM>>>(
            ed, pw1 + l * NC * DIM, pb1 + l * DIM, pw2 + l * DIM * DIM, pb2 + l * DIM);
        k_update<<<NATOMS, DIM>>>(qw1 + l * DIM * DIM, qb1 + l * DIM,
                                  qw2 + l * DIM * DIM, qb2 + l * DIM);
    }
    k_atomupd<<<NATOMS, DIM>>>(auw1, aub1, auw2, aub2);
    int blocks = 1184;
    k_readout<<<blocks, 128>>>(ed, src, dst, row1, rob1, row2, rob2,
                               (float2*)d_out, blocks * 4);
}

// round 3
// speedup vs baseline: 6.3187x; 6.3187x over previous
#include <cuda_runtime.h>

#define NATOMS 768
#define NM1 767
#define NEDGE (NATOMS * NM1)
#define DIM 64
#define NC 50
#define NCONV 3
#define ISLICE 96           // 8 source slices per destination
#define RTAB 2048
#define DSCALE (2047.0f / 5.0f)
#define DSTEP  (5.0f / 2047.0f)

// -------- scratch (device globals; no runtime allocation) --------
__device__ float g_h[NATOMS * DIM];
__device__ float g_nw[NATOMS * DIM];
__device__ float g_agg[NATOMS * DIM];
__device__ float g_ha[NATOMS];
// interleaved lerp tables: element (r, t) = (f(d_r)[t], f(d_{r+1})[t])
__device__ float2 g_tabI[NCONV][RTAB * DIM];   // conv edge filters, 3 MB
__device__ float2 g_roI[RTAB * DIM];           // readout rbf contribution, 1 MB

__device__ __forceinline__ float sp05(float x) {
    // softplus_bt(x, beta=0.5, thr=14)
    float bx = 0.5f * x;
    return (bx > 14.0f) ? x : 2.0f * log1pf(__expf(bx));
}

// ================= table builders =================
// one block per (row, layer); 64 threads = output dim
__global__ __launch_bounds__(64) void k_build_conv(
    const float* __restrict__ pw1_all, const float* __restrict__ pb1_all,
    const float* __restrict__ pw2_all, const float* __restrict__ pb2_all)
{
    int r = blockIdx.x, l = blockIdx.y, t = threadIdx.x;
    const float* pw1 = pw1_all + l * NC * DIM;
    const float* pb1 = pb1_all + l * DIM;
    const float* pw2 = pw2_all + l * DIM * DIM;
    const float* pb2 = pb2_all + l * DIM;
    float d = (float)r * DSTEP;

    __shared__ float srbf[NC];
    __shared__ float st[DIM];
    if (t < NC) {
        float x = d - (float)t * (5.0f / 49.0f);
        srbf[t] = __expf(-(49.0f / 5.0f) * x * x);
    }
    __syncthreads();
    float a = pb1[t];
#pragma unroll
    for (int k = 0; k < NC; k++) a = fmaf(srbf[k], pw1[k * DIM + t], a);
    st[t] = sp05(a);
    __syncthreads();
    float e = pb2[t];
#pragma unroll
    for (int k = 0; k < DIM; k++) e = fmaf(st[k], pw2[k * DIM + t], e);

    g_tabI[l][r * DIM + t].x = e;
    if (r > 0) g_tabI[l][(r - 1) * DIM + t].y = e;
}

__global__ __launch_bounds__(64) void k_build_ro(const float* __restrict__ ro_w1)
{
    int r = blockIdx.x, t = threadIdx.x;
    float d = (float)r * DSTEP;
    __shared__ float srbf[NC];
    if (t < NC) {
        float x = d - (float)t * (5.0f / 49.0f);
        srbf[t] = __expf(-(49.0f / 5.0f) * x * x);
    }
    __syncthreads();
    float g = 0.f;
#pragma unroll
    for (int k = 0; k < NC; k++) g = fmaf(srbf[k], ro_w1[(2 + k) * DIM + t], g);
    g_roI[r * DIM + t].x = g;
    if (r > 0) g_roI[(r - 1) * DIM + t].y = g;
}

// ================= node kernels (1 block per atom, 64 threads) =================
__device__ __forceinline__ float dot64_sm(const float* __restrict__ s,
                                          const float* __restrict__ W, int t, float bias) {
    const float4* s4 = (const float4*)s;
    float a0 = bias, a1 = 0.f, a2 = 0.f, a3 = 0.f;
#pragma unroll
    for (int k = 0; k < 16; k++) {
        float4 v = s4[k];
        a0 = fmaf(v.x, W[(4 * k + 0) * DIM + t], a0);
        a1 = fmaf(v.y, W[(4 * k + 1) * DIM + t], a1);
        a2 = fmaf(v.z, W[(4 * k + 2) * DIM + t], a2);
        a3 = fmaf(v.w, W[(4 * k + 3) * DIM + t], a3);
    }
    return (a0 + a1) + (a2 + a3);
}

// h = emb[at]; nw = h @ w1[0]; agg = 0
__global__ __launch_bounds__(64) void k_node_first(
    const int* __restrict__ at, const float* __restrict__ emb,
    const float* __restrict__ W)
{
    int n = blockIdx.x, t = threadIdx.x;
    __shared__ float sh[DIM];
    float h = emb[at[n] * DIM + t];
    g_h[n * DIM + t] = h;
    sh[t] = h;
    __syncthreads();
    g_nw[n * DIM + t] = dot64_sm(sh, W, t, 0.f);
    g_agg[n * DIM + t] = 0.f;
}

// h += MLP_q(agg); nw = h @ Wnext; agg = 0
__global__ __launch_bounds__(64) void k_node_mid(
    const float* __restrict__ qw1, const float* __restrict__ qb1,
    const float* __restrict__ qw2, const float* __restrict__ qb2,
    const float* __restrict__ Wnext)
{
    int n = blockIdx.x, t = threadIdx.x;
    __shared__ float sa[DIM], st[DIM], sh[DIM];
    sa[t] = g_agg[n * DIM + t];
    __syncthreads();
    st[t] = sp05(dot64_sm(sa, qw1, t, qb1[t]));
    __syncthreads();
    float u = dot64_sm(st, qw2, t, qb2[t]);
    float h = g_h[n * DIM + t] + u;
    g_h[n * DIM + t] = h;
    sh[t] = h;
    __syncthreads();
    g_nw[n * DIM + t] = dot64_sm(sh, Wnext, t, 0.f);
    g_agg[n * DIM + t] = 0.f;
}

// h += MLP_q(agg); ha = shiftsoftplus(h@au_w1+b1)@au_w2 + b2
__global__ __launch_bounds__(64) void k_node_last(
    const float* __restrict__ qw1, const float* __restrict__ qb1,
    const float* __restrict__ qw2, const float* __restrict__ qb2,
    const float* __restrict__ auw1, const float* __restrict__ aub1,
    const float* __restrict__ auw2, const float* __restrict__ aub2)
{
    int n = blockIdx.x, t = threadIdx.x;
    __shared__ float sa[DIM], st[DIM], sh[DIM], red[DIM];
    sa[t] = g_agg[n * DIM + t];
    __syncthreads();
    st[t] = sp05(dot64_sm(sa, qw1, t, qb1[t]));
    __syncthreads();
    float h = g_h[n * DIM + t] + dot64_sm(st, qw2, t, qb2[t]);
    sh[t] = h;
    __syncthreads();
    float a = dot64_sm(sh, auw1, t, aub1[t]);
    float hid = ((a > 20.0f) ? a : log1pf(__expf(a))) - 0.69314718055994530942f;
    red[t] = hid * auw2[t];
    __syncthreads();
    if (t < 32) red[t] += red[t + 32];
    __syncthreads();
    if (t < 32) {
        float v = red[t];
#pragma unroll
        for (int o = 16; o; o >>= 1) v += __shfl_xor_sync(0xffffffffu, v, o);
        if (t == 0) g_ha[n] = v + aub2[0];
    }
}

// ================= fused LUT edge conv =================
// grid (8 slices, 768 dst). 32 threads; lane handles dims (2t, 2t+1).
// agg[j] += sum_i nw[i] * lerp(tab, d_ij)
__global__ __launch_bounds__(32) void k_conv(const float* __restrict__ ed, int l)
{
    int j = blockIdx.y, t = threadIdx.x;
    int i = blockIdx.x * ISLICE;
    int iend = i + ISLICE;
    const float2* __restrict__ tab = g_tabI[l];
    const float* __restrict__ edj = ed + j;          // ed[i*NM1 + j - (j>i)]
    float acc0 = 0.f, acc1 = 0.f;
#pragma unroll 4
    for (; i < iend; i++) {
        if (i == j) continue;
        float d = __ldg(&edj[i * NM1 - (j > i ? 1 : 0)]);
        float x = d * DSCALE;
        int r = (int)x;
        r = min(r, RTAB - 2);
        float f = x - (float)r;
        float4 p = __ldg((const float4*)(tab + r * DIM) + t);   // (e_r[d0], e_r1[d0], e_r[d1], e_r1[d1])
        float2 nw = __ldg((const float2*)(g_nw + i * DIM) + t);
        float ev0 = fmaf(f, p.y - p.x, p.x);
        float ev1 = fmaf(f, p.w - p.z, p.z);
        acc0 = fmaf(nw.x, ev0, acc0);
        acc1 = fmaf(nw.y, ev1, acc1);
    }
    atomicAdd(&g_agg[j * DIM + 2 * t], acc0);
    atomicAdd(&g_agg[j * DIM + 2 * t + 1], acc1);
}

// ================= LUT readout =================
// warp per edge, grid-stride; lane handles hidden dims (lane, lane+32)
__global__ __launch_bounds__(256) void k_readout(
    const float* __restrict__ ed,
    const float* __restrict__ w1, const float* __restrict__ b1,
    const float* __restrict__ w2, const float* __restrict__ b2,
    float2* __restrict__ out, int nwarps_total)
{
    int lane = threadIdx.x & 31;
    int gw = blockIdx.x * 8 + (threadIdx.x >> 5);
    int t0 = lane, t1 = lane + 32;

    float wsrc0 = w1[t0],        wdst0 = w1[DIM + t0];
    float wsrc1 = w1[t1],        wdst1 = w1[DIM + t1];
    float bb0 = b1[t0],          bb1 = b1[t1];
    float w200 = w2[t0 * 2],     w201 = w2[t0 * 2 + 1];
    float w210 = w2[t1 * 2],     w211 = w2[t1 * 2 + 1];
    float lb0 = b2[0],           lb1 = b2[1];

    for (int e = gw; e < NEDGE; e += nwarps_total) {
        int i = e / NM1;
        int jj = e - i * NM1;
        int j = jj + (jj >= i ? 1 : 0);
        float d = __ldg(&ed[e]);
        float hai = __ldg(&g_ha[i]);
        float haj = __ldg(&g_ha[j]);

        float x = d * DSCALE;
        int r = (int)x;
        r = min(r, RTAB - 2);
        float f = x - (float)r;
        const float2* g = g_roI + r * DIM;
        float2 p0 = __ldg(g + t0);
        float2 p1 = __ldg(g + t1);
        float g0 = fmaf(f, p0.y - p0.x, p0.x);
        float g1 = fmaf(f, p1.y - p1.x, p1.x);

        float h0 = fmaxf(fmaf(hai, wsrc0, fmaf(haj, wdst0, bb0 + g0)), 0.f);
        float h1 = fmaxf(fmaf(hai, wsrc1, fmaf(haj, wdst1, bb1 + g1)), 0.f);
        float l0 = fmaf(h0, w200, h1 * w210);
        float l1 = fmaf(h0, w201, h1 * w211);
#pragma unroll
        for (int o = 16; o; o >>= 1) {
            l0 += __shfl_xor_sync(0xffffffffu, l0, o);
            l1 += __shfl_xor_sync(0xffffffffu, l1, o);
        }
        if (lane == 0) {
            l0 += lb0; l1 += lb1;
            float m = fmaxf(l0, l1);
            float e0 = __expf(l0 - m), e1 = __expf(l1 - m);
            float inv = 1.0f / (e0 + e1);
            out[e] = make_float2(e0 * inv, e1 * inv);
        }
    }
}

extern "C" void kernel_launch(void* const* d_in, const int* in_sizes, int n_in,
                              void* d_out, int out_size) {
    const int*   at   = (const int*)d_in[0];
    const float* ed   = (const float*)d_in[1];
    // d_in[2]=src, d_in[3]=dst unused (indices derived analytically)
    const float* emb  = (const float*)d_in[4];
    const float* w1   = (const float*)d_in[5];
    const float* pw1  = (const float*)d_in[6];
    const float* pb1  = (const float*)d_in[7];
    const float* pw2  = (const float*)d_in[8];
    const float* pb2  = (const float*)d_in[9];
    const float* qw1  = (const float*)d_in[10];
    const float* qb1  = (const float*)d_in[11];
    const float* qw2  = (const float*)d_in[12];
    const float* qb2  = (const float*)d_in[13];
    const float* auw1 = (const float*)d_in[14];
    const float* aub1 = (const float*)d_in[15];
    const float* auw2 = (const float*)d_in[16];
    const float* aub2 = (const float*)d_in[17];
    const float* row1 = (const float*)d_in[18];
    const float* rob1 = (const float*)d_in[19];
    const float* row2 = (const float*)d_in[20];
    const float* rob2 = (const float*)d_in[21];

    // build LUTs (cheap, deterministic every call)
    k_build_conv<<<dim3(RTAB, NCONV), DIM>>>(pw1, pb1, pw2, pb2);
    k_build_ro<<<RTAB, DIM>>>(row1);

    k_node_first<<<NATOMS, DIM>>>(at, emb, w1);
    for (int l = 0; l < NCONV; l++) {
        k_conv<<<dim3(NATOMS / ISLICE, NATOMS), 32>>>(ed, l);
        if (l < NCONV - 1)
            k_node_mid<<<NATOMS, DIM>>>(qw1 + l * DIM * DIM, qb1 + l * DIM,
                                        qw2 + l * DIM * DIM, qb2 + l * DIM,
                                        w1 + (l + 1) * DIM * DIM);
    }
    k_node_last<<<NATOMS, DIM>>>(qw1 + 2 * DIM * DIM, qb1 + 2 * DIM,
                                 qw2 + 2 * DIM * DIM, qb2 + 2 * DIM,
                                 auw1, aub1, auw2, aub2);
    int blocks = 1184;
    k_readout<<<blocks, 256>>>(ed, row1, rob1, row2, rob2,
                               (float2*)d_out, blocks * 8);
}

// round 6
// speedup vs baseline: 12.1053x; 1.9158x over previous
#include <cuda_runtime.h>

#define NATOMS 768
#define NM1 767
#define NEDGE (NATOMS * NM1)
#define DIM 64
#define NC 50
#define NCONV 3
#define ISLICE 64           // 12 source slices per destination
#define RTAB 2048
#define DSCALE (2047.0f / 5.0f)
#define DSTEP  (5.0f / 2047.0f)

// -------- scratch (device globals; no runtime allocation) --------
__device__ float g_h[NATOMS * DIM];
__device__ float g_nw[NATOMS * DIM];
__device__ float g_agg[NATOMS * DIM];
__device__ float g_ha[NATOMS];
// interleaved lerp tables: element (r, t) = (f(d_r)[t], f(d_{r+1})[t])
__device__ float2 g_tabI[NCONV][RTAB * DIM];   // conv edge filters, 3 MB
__device__ float2 g_roI[RTAB * DIM];           // readout rbf contribution, 1 MB

__device__ __forceinline__ float sp05(float x) {
    float bx = 0.5f * x;
    return (bx > 14.0f) ? x : 2.0f * log1pf(__expf(bx));
}

// ================= table builders =================
__global__ __launch_bounds__(64) void k_build_conv(
    const float* __restrict__ pw1_all, const float* __restrict__ pb1_all,
    const float* __restrict__ pw2_all, const float* __restrict__ pb2_all)
{
    int r = blockIdx.x, l = blockIdx.y, t = threadIdx.x;
    const float* pw1 = pw1_all + l * NC * DIM;
    const float* pb1 = pb1_all + l * DIM;
    const float* pw2 = pw2_all + l * DIM * DIM;
    const float* pb2 = pb2_all + l * DIM;
    float d = (float)r * DSTEP;

    __shared__ float srbf[NC];
    __shared__ float st[DIM];
    if (t < NC) {
        float x = d - (float)t * (5.0f / 49.0f);
        srbf[t] = __expf(-(49.0f / 5.0f) * x * x);
    }
    __syncthreads();
    float a = pb1[t];
#pragma unroll
    for (int k = 0; k < NC; k++) a = fmaf(srbf[k], pw1[k * DIM + t], a);
    st[t] = sp05(a);
    __syncthreads();
    float e = pb2[t];
#pragma unroll
    for (int k = 0; k < DIM; k++) e = fmaf(st[k], pw2[k * DIM + t], e);

    g_tabI[l][r * DIM + t].x = e;
    if (r > 0) g_tabI[l][(r - 1) * DIM + t].y = e;
}

__global__ __launch_bounds__(64) void k_build_ro(const float* __restrict__ ro_w1)
{
    int r = blockIdx.x, t = threadIdx.x;
    float d = (float)r * DSTEP;
    __shared__ float srbf[NC];
    if (t < NC) {
        float x = d - (float)t * (5.0f / 49.0f);
        srbf[t] = __expf(-(49.0f / 5.0f) * x * x);
    }
    __syncthreads();
    float g = 0.f;
#pragma unroll
    for (int k = 0; k < NC; k++) g = fmaf(srbf[k], ro_w1[(2 + k) * DIM + t], g);
    g_roI[r * DIM + t].x = g;
    if (r > 0) g_roI[(r - 1) * DIM + t].y = g;
}

// ================= node kernels =================
__device__ __forceinline__ float dot64_sm(const float* __restrict__ s,
                                          const float* __restrict__ W, int t, float bias) {
    const float4* s4 = (const float4*)s;
    float a0 = bias, a1 = 0.f, a2 = 0.f, a3 = 0.f;
#pragma unroll
    for (int k = 0; k < 16; k++) {
        float4 v = s4[k];
        a0 = fmaf(v.x, W[(4 * k + 0) * DIM + t], a0);
        a1 = fmaf(v.y, W[(4 * k + 1) * DIM + t], a1);
        a2 = fmaf(v.z, W[(4 * k + 2) * DIM + t], a2);
        a3 = fmaf(v.w, W[(4 * k + 3) * DIM + t], a3);
    }
    return (a0 + a1) + (a2 + a3);
}

__global__ __launch_bounds__(64) void k_node_first(
    const int* __restrict__ at, const float* __restrict__ emb,
    const float* __restrict__ W)
{
    int n = blockIdx.x, t = threadIdx.x;
    __shared__ float sh[DIM];
    float h = emb[at[n] * DIM + t];
    g_h[n * DIM + t] = h;
    sh[t] = h;
    __syncthreads();
    g_nw[n * DIM + t] = dot64_sm(sh, W, t, 0.f);
    g_agg[n * DIM + t] = 0.f;
}

__global__ __launch_bounds__(64) void k_node_mid(
    const float* __restrict__ qw1, const float* __restrict__ qb1,
    const float* __restrict__ qw2, const float* __restrict__ qb2,
    const float* __restrict__ Wnext)
{
    int n = blockIdx.x, t = threadIdx.x;
    __shared__ float sa[DIM], st[DIM], sh[DIM];
    sa[t] = g_agg[n * DIM + t];
    __syncthreads();
    st[t] = sp05(dot64_sm(sa, qw1, t, qb1[t]));
    __syncthreads();
    float u = dot64_sm(st, qw2, t, qb2[t]);
    float h = g_h[n * DIM + t] + u;
    g_h[n * DIM + t] = h;
    sh[t] = h;
    __syncthreads();
    g_nw[n * DIM + t] = dot64_sm(sh, Wnext, t, 0.f);
    g_agg[n * DIM + t] = 0.f;
}

__global__ __launch_bounds__(64) void k_node_last(
    const float* __restrict__ qw1, const float* __restrict__ qb1,
    const float* __restrict__ qw2, const float* __restrict__ qb2,
    const float* __restrict__ auw1, const float* __restrict__ aub1,
    const float* __restrict__ auw2, const float* __restrict__ aub2)
{
    int n = blockIdx.x, t = threadIdx.x;
    __shared__ float sa[DIM], st[DIM], sh[DIM], red[DIM];
    sa[t] = g_agg[n * DIM + t];
    __syncthreads();
    st[t] = sp05(dot64_sm(sa, qw1, t, qb1[t]));
    __syncthreads();
    float h = g_h[n * DIM + t] + dot64_sm(st, qw2, t, qb2[t]);
    sh[t] = h;
    __syncthreads();
    float a = dot64_sm(sh, auw1, t, aub1[t]);
    float hid = ((a > 20.0f) ? a : log1pf(__expf(a))) - 0.69314718055994530942f;
    red[t] = hid * auw2[t];
    __syncthreads();
    if (t < 32) red[t] += red[t + 32];
    __syncthreads();
    if (t < 32) {
        float v = red[t];
#pragma unroll
        for (int o = 16; o; o >>= 1) v += __shfl_xor_sync(0xffffffffu, v, o);
        if (t == 0) g_ha[n] = v + aub2[0];
    }
}

// ================= fused LUT edge conv =================
// grid (12 slices, 96 j-groups), 256 threads = 8 warps; warp w -> j = by*8+w.
// Distances for the (ISLICE x 8) patch staged coalesced into smem (pre-scaled),
// breaking the LDG(dist)->LDG(table) dependent chain. lane covers dims
// (2*lane, 2*lane+1); branchless i==j via clamp + predicated accumulate.
__global__ __launch_bounds__(256) void k_conv(const float* __restrict__ ed,
                                              const float2* __restrict__ tab)
{
    __shared__ float s_x[ISLICE * 8];    // [i_local][j_local], pre-scaled
    int lane = threadIdx.x & 31;
    int w = threadIdx.x >> 5;
    int jbase = blockIdx.y * 8;
    int j = jbase + w;
    int i0 = blockIdx.x * ISLICE;

    // ---- stage distances (coalesced: 8 consecutive j per i-row) ----
    for (int idx = threadIdx.x; idx < ISLICE * 8; idx += 256) {
        int il = idx >> 3, jl = idx & 7;
        int i = i0 + il, jj = jbase + jl;
        int eidx = i * NM1 + jj - (jj > i ? 1 : 0);
        eidx = min(eidx, NEDGE - 1);               // i==j clamps; masked in main loop
        s_x[idx] = __ldg(ed + eidx) * DSCALE;
    }
    __syncthreads();

    const float* sxw = s_x + w;
    float acc0 = 0.f, acc1 = 0.f;
#pragma unroll 2
    for (int ib = 0; ib < ISLICE; ib += 4) {
        float x[4];
#pragma unroll
        for (int k = 0; k < 4; k++) x[k] = sxw[(ib + k) * 8];
#pragma unroll
        for (int k = 0; k < 4; k++) {
            int i = i0 + ib + k;
            int r = min((int)x[k], RTAB - 2);
            float f = x[k] - (float)r;
            float4 p  = __ldg((const float4*)(tab + r * DIM) + lane);
            float2 nw = __ldg((const float2*)(g_nw + i * DIM) + lane);
            float ev0 = fmaf(f, p.y - p.x, p.x);
            float ev1 = fmaf(f, p.w - p.z, p.z);
            if (i != j) {
                acc0 = fmaf(nw.x, ev0, acc0);
                acc1 = fmaf(nw.y, ev1, acc1);
            }
        }
    }
    atomicAdd(&g_agg[j * DIM + 2 * lane], acc0);
    atomicAdd(&g_agg[j * DIM + 2 * lane + 1], acc1);
}

// ================= LUT readout =================
__global__ __launch_bounds__(256) void k_readout(
    const float* __restrict__ ed,
    const float* __restrict__ w1, const float* __restrict__ b1,
    const float* __restrict__ w2, const float* __restrict__ b2,
    float2* __restrict__ out, int nwarps_total)
{
    int lane = threadIdx.x & 31;
    int gw = blockIdx.x * 8 + (threadIdx.x >> 5);
    int t0 = lane, t1 = lane + 32;

    float wsrc0 = w1[t0],        wdst0 = w1[DIM + t0];
    float wsrc1 = w1[t1],        wdst1 = w1[DIM + t1];
    float bb0 = b1[t0],          bb1 = b1[t1];
    float w200 = w2[t0 * 2],     w201 = w2[t0 * 2 + 1];
    float w210 = w2[t1 * 2],     w211 = w2[t1 * 2 + 1];
    float lb0 = b2[0],           lb1 = b2[1];

    for (int e = gw; e < NEDGE; e += nwarps_total) {
        int i = e / NM1;
        int jj = e - i * NM1;
        int j = jj + (jj >= i ? 1 : 0);
        float d = __ldg(&ed[e]);
        float hai = __ldg(&g_ha[i]);
        float haj = __ldg(&g_ha[j]);

        float x = d * DSCALE;
        int r = min((int)x, RTAB - 2);
        float f = x - (float)r;
        const float2* g = g_roI + r * DIM;
        float2 p0 = __ldg(g + t0);
        float2 p1 = __ldg(g + t1);
        float g0 = fmaf(f, p0.y - p0.x, p0.x);
        float g1 = fmaf(f, p1.y - p1.x, p1.x);

        float h0 = fmaxf(fmaf(hai, wsrc0, fmaf(haj, wdst0, bb0 + g0)), 0.f);
        float h1 = fmaxf(fmaf(hai, wsrc1, fmaf(haj, wdst1, bb1 + g1)), 0.f);
        float l0 = fmaf(h0, w200, h1 * w210);
        float l1 = fmaf(h0, w201, h1 * w211);
#pragma unroll
        for (int o = 16; o; o >>= 1) {
            l0 += __shfl_xor_sync(0xffffffffu, l0, o);
            l1 += __shfl_xor_sync(0xffffffffu, l1, o);
        }
        if (lane == 0) {
            l0 += lb0; l1 += lb1;
            float m = fmaxf(l0, l1);
            float e0 = __expf(l0 - m), e1 = __expf(l1 - m);
            float inv = 1.0f / (e0 + e1);
            out[e] = make_float2(e0 * inv, e1 * inv);
        }
    }
}

extern "C" void kernel_launch(void* const* d_in, const int* in_sizes, int n_in,
                              void* d_out, int out_size) {
    const int*   at   = (const int*)d_in[0];
    const float* ed   = (const float*)d_in[1];
    const float* emb  = (const float*)d_in[4];
    const float* w1   = (const float*)d_in[5];
    const float* pw1  = (const float*)d_in[6];
    const float* pb1  = (const float*)d_in[7];
    const float* pw2  = (const float*)d_in[8];
    const float* pb2  = (const float*)d_in[9];
    const float* qw1  = (const float*)d_in[10];
    const float* qb1  = (const float*)d_in[11];
    const float* qw2  = (const float*)d_in[12];
    const float* qb2  = (const float*)d_in[13];
    const float* auw1 = (const float*)d_in[14];
    const float* aub1 = (const float*)d_in[15];
    const float* auw2 = (const float*)d_in[16];
    const float* aub2 = (const float*)d_in[17];
    const float* row1 = (const float*)d_in[18];
    const float* rob1 = (const float*)d_in[19];
    const float* row2 = (const float*)d_in[20];
    const float* rob2 = (const float*)d_in[21];

    float2* tab0; cudaGetSymbolAddress((void**)&tab0, g_tabI);

    k_build_conv<<<dim3(RTAB, NCONV), DIM>>>(pw1, pb1, pw2, pb2);
    k_build_ro<<<RTAB, DIM>>>(row1);

    k_node_first<<<NATOMS, DIM>>>(at, emb, w1);
    for (int l = 0; l < NCONV; l++) {
        k_conv<<<dim3(NATOMS / ISLICE, NATOMS / 8), 256>>>(ed, tab0 + l * RTAB * DIM);
        if (l < NCONV - 1)
            k_node_mid<<<NATOMS, DIM>>>(qw1 + l * DIM * DIM, qb1 + l * DIM,
                                        qw2 + l * DIM * DIM, qb2 + l * DIM,
                                        w1 + (l + 1) * DIM * DIM);
    }
    k_node_last<<<NATOMS, DIM>>>(qw1 + 2 * DIM * DIM, qb1 + 2 * DIM,
                                 qw2 + 2 * DIM * DIM, qb2 + 2 * DIM,
                                 auw1, aub1, auw2, aub2);
    int blocks = 1184;
    k_readout<<<blocks, 256>>>(ed, row1, rob1, row2, rob2,
                               (float2*)d_out, blocks * 8);
}